// round 10
// baseline (speedup 1.0000x reference)
#include <cuda_runtime.h>
#include <cuda_bf16.h>
#include <math.h>
#include <float.h>

// Geometry
#define NROWS   131072
#define KCODE   512
#define BCH     262144           // 64*64*64 batch stride in z (B,C,H,W)
#define TILEM   128
#define NTILES  1024             // NROWS / 128
#define GRID    148
#define TPB     512

// d_out layout (fp32, outputs concatenated)
#define OFF_LOSS 0
#define OFF_ZQ   1
#define OFF_PERP 8388609
#define OFF_ENC  8388610ULL
#define OFF_CODE 75497474ULL

// smem byte offsets
#define SM_WB    0         // 65536: bf16 weight [512][64], SW128 rows of 128B
#define SM_ZB    65536     // 16384: bf16 z [128][64], SW128
#define SM_ZS    81920     // 33024: fp32 z, zs[d*129 + r]
#define SM_WN    114944    // 2048 : ||w_c||^2 exact
#define SM_ZN    116992    // 512  : ||z_r||^2 exact
#define SM_CM    117504    // 32768: chunk minima [128 rows][64 chunks] f32
#define SM_CODE  150272    // 512  : int code per row
#define SM_HIST  150784    // 2048 : int histogram
#define SM_LRED  152832    // 64
#define SM_SMAX  152896    // 4
#define SM_FLAG  152900    // 4
#define SM_TOTB  152960

#define SWZ(off) ((off) ^ (((off) >> 3) & 0x70))

__device__ float        g_loss_part[GRID];
__device__ int          g_hist_part[GRID * KCODE];
__device__ unsigned int g_done;   // zero-init; last block resets to 0

__device__ __forceinline__ unsigned orderable(float s) {
    unsigned ub = __float_as_uint(s);
    return (ub & 0x80000000u) ? ~ub : (ub | 0x80000000u);
}
__device__ __forceinline__ void ldsm_x4(unsigned& r0, unsigned& r1,
                                        unsigned& r2, unsigned& r3, unsigned a) {
    asm volatile("ldmatrix.sync.aligned.m8n8.x4.shared.b16 {%0,%1,%2,%3}, [%4];"
                 : "=r"(r0), "=r"(r1), "=r"(r2), "=r"(r3) : "r"(a));
}
__device__ __forceinline__ void mma16816(float* d, const unsigned* a,
                                         unsigned b0, unsigned b1) {
    asm volatile(
        "mma.sync.aligned.m16n8k16.row.col.f32.bf16.bf16.f32 "
        "{%0,%1,%2,%3}, {%4,%5,%6,%7}, {%8,%9}, {%0,%1,%2,%3};"
        : "+f"(d[0]), "+f"(d[1]), "+f"(d[2]), "+f"(d[3])
        : "r"(a[0]), "r"(a[1]), "r"(a[2]), "r"(a[3]), "r"(b0), "r"(b1));
}

__global__ __launch_bounds__(TPB, 1)
void vq_fused(const float* __restrict__ z, const float* __restrict__ w,
              float* __restrict__ dout) {
    extern __shared__ char smem[];
    const unsigned sb = (unsigned)__cvta_generic_to_shared(smem);

    float*    zs   = (float*)(smem + SM_ZS);
    float*    wn   = (float*)(smem + SM_WN);
    float*    zn   = (float*)(smem + SM_ZN);
    float*    cm   = (float*)(smem + SM_CM);
    int*      rcd  = (int*)(smem + SM_CODE);
    int*      hist = (int*)(smem + SM_HIST);
    float*    lred = (float*)(smem + SM_LRED);
    float*    smax = (float*)(smem + SM_SMAX);
    unsigned* sfin = (unsigned*)(smem + SM_FLAG);

    const int tid  = threadIdx.x;
    const int wid  = tid >> 5;
    const int lane = tid & 31;
    const int rg   = (wid >> 1) * 16;   // row group base
    const int half = wid & 1;           // code half (0: 0-255, 1: 256-511)

    hist[tid] = 0;

    // ---- stage weight: bf16 SW128 + exact sequential wn ----
    {
        const int c = tid;
        const float* wr = w + c * 64;
        float v0 = wr[0];
        float s  = __fmul_rn(v0, v0);
        *(__nv_bfloat16*)(smem + SM_WB + SWZ(c * 128)) = __float2bfloat16(v0);
#pragma unroll
        for (int d = 1; d < 64; ++d) {
            float v = wr[d];
            s = __fadd_rn(s, __fmul_rn(v, v));
            *(__nv_bfloat16*)(smem + SM_WB + SWZ(c * 128 + d * 2)) = __float2bfloat16(v);
        }
        wn[c] = s;
    }
    __syncthreads();
    if (wid == 0) {
        float m = 0.0f;
#pragma unroll
        for (int j = 0; j < 16; ++j) m = fmaxf(m, wn[lane + 32 * j]);
#pragma unroll
        for (int off = 16; off > 0; off >>= 1)
            m = fmaxf(m, __shfl_down_sync(0xFFFFFFFFu, m, off));
        if (lane == 0) *smax = sqrtf(m);
    }
    __syncthreads();
    const float Smax = *smax;

    float ls = 0.0f;

    for (int tile = blockIdx.x; tile < NTILES; tile += GRID) {
        const int    n0  = tile * TILEM;
        const int    b   = n0 >> 12;
        const int    rem = n0 & 4095;
        const float* zg  = z + (size_t)b * BCH + rem;

        // ---- stage z: fp32 (pitch 129) + bf16 SW128 ----
#pragma unroll
        for (int pass = 0; pass < 16; ++pass) {
            int d = pass * 4 + (tid >> 7);
            int r = tid & 127;
            float v = zg[((size_t)d << 12) + r];
            zs[d * 129 + r] = v;
            *(__nv_bfloat16*)(smem + SM_ZB + SWZ(r * 128 + d * 2)) = __float2bfloat16(v);
        }
        __syncthreads();

        // zn: exact sequential (reference order)
        if (tid < 128) {
            float v = zs[tid];
            float s = __fmul_rn(v, v);
#pragma unroll
            for (int d = 1; d < 64; ++d) {
                v = zs[d * 129 + tid];
                s = __fadd_rn(s, __fmul_rn(v, v));
            }
            zn[tid] = s;
        }
        __syncthreads();

        // ---- A fragments: z rows rg..rg+15, all 64 k (resident) ----
        unsigned A[4][4];
#pragma unroll
        for (int ks = 0; ks < 4; ++ks) {
            int t  = lane >> 3, wi = lane & 7;
            int m  = rg + (t & 1) * 8 + wi;
            int kb = ks * 16 + (t >> 1) * 8;
            ldsm_x4(A[ks][0], A[ks][1], A[ks][2], A[ks][3],
                    sb + SM_ZB + SWZ((unsigned)(m * 128 + kb * 2)));
        }

        // ---- chunk loop: 8 codes per chunk, approx scores -> chunk minima ----
        const int cl = lane & 3, rl = lane >> 2;
#pragma unroll 2
        for (int ch = 0; ch < 32; ++ch) {
            const int cb  = half * 256 + ch * 8;
            const int chg = half * 32 + ch;
            unsigned b0, b1, b2, b3, b4, b5, b6, b7;
            {
                int code = cb + (lane & 7);
                int kb   = (lane >> 3) * 8;
                ldsm_x4(b0, b1, b2, b3,
                        sb + SM_WB + SWZ((unsigned)(code * 128 + kb * 2)));
                ldsm_x4(b4, b5, b6, b7,
                        sb + SM_WB + SWZ((unsigned)(code * 128 + (kb + 32) * 2)));
            }
            float acc[4] = {0.f, 0.f, 0.f, 0.f};
            mma16816(acc, A[0], b0, b1);
            mma16816(acc, A[1], b2, b3);
            mma16816(acc, A[2], b4, b5);
            mma16816(acc, A[3], b6, b7);

            const float wn0 = wn[cb + cl * 2], wn1 = wn[cb + cl * 2 + 1];
            float m1 = fminf(fmaf(-2.0f, acc[0], wn0), fmaf(-2.0f, acc[1], wn1));
            float m2 = fminf(fmaf(-2.0f, acc[2], wn0), fmaf(-2.0f, acc[3], wn1));
            m1 = fminf(m1, __shfl_xor_sync(0xFFFFFFFFu, m1, 1));
            m1 = fminf(m1, __shfl_xor_sync(0xFFFFFFFFu, m1, 2));
            m2 = fminf(m2, __shfl_xor_sync(0xFFFFFFFFu, m2, 1));
            m2 = fminf(m2, __shfl_xor_sync(0xFFFFFFFFu, m2, 2));
            if (cl == 0) {
                cm[(rg + rl) * 64 + chg]     = m1;
                cm[(rg + 8 + rl) * 64 + chg] = m2;
            }
        }
        __syncthreads();

        // ---- scan + certified exact re-score (4 threads per row) ----
        {
            const int r = tid >> 2, p = tid & 3;
            float loc[16];
            float rmn = FLT_MAX;
            const float* cmr = cm + r * 64;
#pragma unroll
            for (int j = 0; j < 16; ++j) {
                loc[j] = cmr[p + 4 * j];
                rmn = fminf(rmn, loc[j]);
            }
            rmn = fminf(rmn, __shfl_xor_sync(0xFFFFFFFFu, rmn, 1));
            rmn = fminf(rmn, __shfl_xor_sync(0xFFFFFFFFu, rmn, 2));
            const float znr = zn[r];
            const float eps = ldexpf(sqrtf(znr) * Smax, -7) + 1e-9f;
            const float thr = rmn + 2.0f * eps;

            unsigned long long key = 0xFFFFFFFFFFFFFFFFULL;
#pragma unroll 1
            for (int j = 0; j < 16; ++j) {
                if (loc[j] > thr) continue;
                const int chg = p + 4 * j;
#pragma unroll 1
                for (int jj = 0; jj < 8; ++jj) {
                    const int c = chg * 8 + jj;
                    const float4* wr = (const float4*)(w + (size_t)c * 64);
                    float dot = 0.0f;
#pragma unroll
                    for (int q = 0; q < 16; ++q) {
                        float4 wv = wr[q];
                        dot = fmaf(zs[(4 * q)     * 129 + r], wv.x, dot);
                        dot = fmaf(zs[(4 * q + 1) * 129 + r], wv.y, dot);
                        dot = fmaf(zs[(4 * q + 2) * 129 + r], wv.z, dot);
                        dot = fmaf(zs[(4 * q + 3) * 129 + r], wv.w, dot);
                    }
                    float es = __fsub_rn(__fadd_rn(znr, wn[c]), __fadd_rn(dot, dot));
                    unsigned long long k =
                        ((unsigned long long)orderable(es) << 32) | (unsigned)c;
                    if (k < key) key = k;
                }
            }
            unsigned long long o = __shfl_xor_sync(0xFFFFFFFFu, key, 1);
            if (o < key) key = o;
            o = __shfl_xor_sync(0xFFFFFFFFu, key, 2);
            if (o < key) key = o;
            if (p == 0) {
                int code = (int)(unsigned)(key & 0xFFFFFFFFULL);
                rcd[r] = code;
                dout[OFF_CODE + (size_t)(n0 + r)] = (float)code;
                atomicAdd(&hist[code], 1);
            }
        }
        __syncthreads();

        // ---- zq + loss (coalesced by r) ----
        float* zqg = dout + OFF_ZQ + (size_t)b * BCH + rem;
#pragma unroll
        for (int pass = 0; pass < 16; ++pass) {
            int d  = pass * 4 + (tid >> 7);
            int rr = tid & 127;
            int code = rcd[rr];
            float zv = zs[d * 129 + rr];
            float wv = w[(size_t)code * 64 + d];
            float df = __fsub_rn(wv, zv);
            ls = fmaf(df, df, ls);
            zqg[((size_t)d << 12) + rr] = __fadd_rn(zv, df);
        }

        // ---- encodings one-hot (float2, 8B-aligned region) ----
        float2* encp = (float2*)(dout + OFF_ENC);
#pragma unroll 8
        for (int pass = 0; pass < 64; ++pass) {
            int e  = pass * 512 + tid;
            int rr = e >> 8;
            int c2 = e & 255;
            int code = rcd[rr];
            float2 v = make_float2(0.0f, 0.0f);
            if (c2 == (code >> 1)) { if (code & 1) v.y = 1.0f; else v.x = 1.0f; }
            encp[(size_t)(n0 + rr) * 256 + c2] = v;
        }
        __syncthreads();   // protect zs/ZB/rcd before next tile staging
    }

    // ---- per-block partials ----
    float lw = ls;
#pragma unroll
    for (int off = 16; off > 0; off >>= 1)
        lw += __shfl_down_sync(0xFFFFFFFFu, lw, off);
    if (lane == 0) lred[wid] = lw;
    __syncthreads();
    if (tid == 0) {
        float t = 0.0f;
#pragma unroll
        for (int i = 0; i < 16; ++i) t += lred[i];
        g_loss_part[blockIdx.x] = t;
    }
    g_hist_part[blockIdx.x * KCODE + tid] = hist[tid];

    // ---- last-block finalize (graph-replay safe: resets g_done) ----
    __threadfence();
    if (tid == 0) *sfin = (atomicAdd(&g_done, 1u) == GRID - 1);
    __syncthreads();
    if (*sfin) {
        int cnt = 0;
        for (int bb = 0; bb < GRID; ++bb) cnt += g_hist_part[bb * KCODE + tid];
        float em = (float)cnt * (1.0f / 131072.0f);
        float v  = em * logf(__fadd_rn(em, 1e-10f));
#pragma unroll
        for (int off = 16; off > 0; off >>= 1)
            v += __shfl_down_sync(0xFFFFFFFFu, v, off);
        if (lane == 0) lred[wid] = v;
        __syncthreads();
        if (wid == 0) {
            float s = (lane < 16) ? lred[lane] : 0.0f;
#pragma unroll
            for (int off = 8; off > 0; off >>= 1)
                s += __shfl_down_sync(0xFFFFFFFFu, s, off);
            if (lane == 0) dout[OFF_PERP] = expf(-s);
        }
        if (wid == 1) {
            float s = 0.0f;
            for (int i = lane; i < GRID; i += 32) s += g_loss_part[i];
#pragma unroll
            for (int off = 16; off > 0; off >>= 1)
                s += __shfl_down_sync(0xFFFFFFFFu, s, off);
            if (lane == 0) {
                float m = s * (1.0f / 8388608.0f);
                dout[OFF_LOSS] = __fadd_rn(m, __fmul_rn(0.25f, m));
            }
        }
        __syncthreads();
        if (tid == 0) g_done = 0;
    }
}

extern "C" void kernel_launch(void* const* d_in, const int* in_sizes, int n_in,
                              void* d_out, int out_size) {
    const float* z = (const float*)d_in[0];
    const float* w = (const float*)d_in[1];
    float* out = (float*)d_out;

    cudaFuncSetAttribute(vq_fused, cudaFuncAttributeMaxDynamicSharedMemorySize,
                         SM_TOTB);
    vq_fused<<<GRID, TPB, SM_TOTB>>>(z, w, out);
}

// round 12
// speedup vs baseline: 2.2983x; 2.2983x over previous
// R12: identical to R11 (R11 failed on infra "device busy", never executed).
#include <cuda_runtime.h>
#include <math.h>
#include <float.h>

// Geometry
#define NROWS   131072
#define KCODE   512
#define BCH     262144           // 64*64*64 batch stride in z (B,C,H,W)
#define TILEM   128
#define NTILES  1024             // NROWS / 128
#define GRID    148
#define TPB     512

// d_out layout (fp32, outputs concatenated)
#define OFF_LOSS 0
#define OFF_ZQ   1
#define OFF_PERP 8388609
#define OFF_ENC  8388610ULL
#define OFF_CODE 75497474ULL

// smem float offsets
#define S_ZT    0        // [16384] z tile pair layout: zt[(p*128+r)*2 + (d&1)], p=d>>1
#define S_WP    16384    // [32768] weight: wp[d*512 + c]
#define S_WN    49152    // [512]
#define S_ZN    49664    // [128]
#define S_PART  49792    // [1024f] = 512 u64: part[r*4 + warpbit*2 + half]
#define S_CODE  50816    // [128] int
#define S_HIST  50944    // [512] int
#define S_LRED  51456    // [16]
#define S_FLAG  51472    // [1]
#define S_TOT   51480

__device__ float        g_loss_part[GRID];
__device__ int          g_hist_part[GRID * KCODE];
__device__ unsigned int g_done;   // zero-init; last block resets it

__device__ __forceinline__ unsigned long long packbb(float x) {
    unsigned long long r;
    asm("mov.b64 %0, {%1,%1};" : "=l"(r) : "f"(x));
    return r;
}
__device__ __forceinline__ void unpack2(unsigned long long a, float& lo, float& hi) {
    asm("mov.b64 {%0,%1}, %2;" : "=f"(lo), "=f"(hi) : "l"(a));
}
__device__ __forceinline__ void lds128(unsigned long long& a, unsigned long long& b,
                                       unsigned addr) {
    asm("ld.shared.v2.u64 {%0,%1}, [%2];" : "=l"(a), "=l"(b) : "r"(addr));
}
__device__ __forceinline__ unsigned long long lds64(unsigned addr) {
    unsigned long long v;
    asm("ld.shared.u64 %0, [%1];" : "=l"(v) : "r"(addr));
    return v;
}
__device__ __forceinline__ void ffma2(unsigned long long& acc,
                                      unsigned long long a, unsigned long long b) {
    asm("fma.rn.f32x2 %0, %1, %2, %0;" : "+l"(acc) : "l"(a), "l"(b));
}
__device__ __forceinline__ unsigned orderable(float s) {
    unsigned ub = __float_as_uint(s);
    return (ub & 0x80000000u) ? ~ub : (ub | 0x80000000u);
}

__global__ __launch_bounds__(TPB, 1)
void vq_fused(const float* __restrict__ z, const float* __restrict__ w,
              float* __restrict__ dout) {
    extern __shared__ float sm[];
    float*              zt   = sm + S_ZT;
    float*              wp   = sm + S_WP;
    float*              wn   = sm + S_WN;
    float*              zn   = sm + S_ZN;
    unsigned long long* part = (unsigned long long*)(sm + S_PART);
    int*                rcd  = (int*)(sm + S_CODE);
    int*                hist = (int*)(sm + S_HIST);
    float*              lred = sm + S_LRED;
    unsigned*           sfin = (unsigned*)(sm + S_FLAG);

    const int tid  = threadIdx.x;
    const int wid  = tid >> 5;
    const int lane = tid & 31;
    const int n    = tid & 63;         // code-thread (0..63)
    const int mth  = tid >> 6;         // row-group thread (0..7), 16 rows each
    const int wbit = (tid >> 5) & 1;   // which warp of the n-range

    // stage weight: wp[d*512 + c] = w[c*64 + d]
    for (int idx = tid; idx < 32768; idx += TPB) {
        int c = idx >> 6, d = idx & 63;
        wp[d * 512 + c] = w[idx];
    }
    hist[tid] = 0;
    __syncthreads();

    // wn[c]: strict sequential sum of rounded squares (reference order)
    {
        float v = wp[tid];
        float s = __fmul_rn(v, v);
#pragma unroll
        for (int d = 1; d < 64; ++d) {
            v = wp[d * 512 + tid];
            s = __fadd_rn(s, __fmul_rn(v, v));
        }
        wn[tid] = s;
    }

    const unsigned smbase = (unsigned)__cvta_generic_to_shared(sm);
    const unsigned zbA0   = smbase + S_ZT * 4 + (unsigned)mth * 128u;  // 16 rows * 8B
    const unsigned wbB0   = smbase + S_WP * 4 + (unsigned)n * 8u;

    float ls = 0.0f;

    for (int tile = blockIdx.x; tile < NTILES; tile += GRID) {
        __syncthreads();   // protect zt/rcd from previous tile epilogue
        const int    n0  = tile * TILEM;
        const int    b   = n0 >> 12;
        const int    rem = n0 & 4095;
        const float* zg  = z + (size_t)b * BCH + rem;

        // stage z tile (128 rows x 64 dims), pair layout
#pragma unroll
        for (int pass = 0; pass < 16; ++pass) {
            int d = pass * 4 + (tid >> 7);
            int r = tid & 127;
            zt[((d >> 1) * 128 + r) * 2 + (d & 1)] = zg[((size_t)d << 12) + r];
        }
        __syncthreads();

        // zn[r]: strict sequential (reference order)
        if (tid < 128) {
            float v = zt[tid * 2];
            float s = __fmul_rn(v, v);
#pragma unroll
            for (int d = 1; d < 64; ++d) {
                v = zt[((d >> 1) * 128 + tid) * 2 + (d & 1)];
                s = __fadd_rn(s, __fmul_rn(v, v));
            }
            zn[tid] = s;
        }
        __syncthreads();

        // ---- two code-half passes: 16 rows x 2 code-pairs per thread ----
#pragma unroll
        for (int half = 0; half < 2; ++half) {
            unsigned long long acc[32];
#pragma unroll
            for (int q = 0; q < 32; ++q) acc[q] = 0ULL;
            const unsigned wbH = wbB0 + (unsigned)half * 1024u;

#pragma unroll 2
            for (int p = 0; p < 32; ++p) {
                unsigned long long za[16];   // za[i] = {z[2p][r0+i], z[2p+1][r0+i]}
#pragma unroll
                for (int q = 0; q < 8; ++q)
                    lds128(za[2 * q], za[2 * q + 1],
                           zbA0 + (unsigned)p * 1024u + (unsigned)q * 16u);
                const unsigned wa = wbH + (unsigned)p * 4096u;
                unsigned long long w00 = lds64(wa);            // d=2p,   j=0
                unsigned long long w01 = lds64(wa + 512u);     // d=2p,   j=1
                unsigned long long w10 = lds64(wa + 2048u);    // d=2p+1, j=0
                unsigned long long w11 = lds64(wa + 2560u);    // d=2p+1, j=1
#pragma unroll
                for (int i = 0; i < 16; ++i) {
                    float lo, hi;
                    unpack2(za[i], lo, hi);
                    unsigned long long zb0 = packbb(lo);
                    unsigned long long zb1 = packbb(hi);
                    ffma2(acc[i * 2],     zb0, w00);
                    ffma2(acc[i * 2],     zb1, w10);
                    ffma2(acc[i * 2 + 1], zb0, w01);
                    ffma2(acc[i * 2 + 1], zb1, w11);
                }
            }

            // per-half epilogue: exact score pipeline + warp-reduced keys
#pragma unroll
            for (int i = 0; i < 16; ++i) {
                const int r = mth * 16 + i;
                const float znr = zn[r];
                unsigned long long key = 0xFFFFFFFFFFFFFFFFULL;
#pragma unroll
                for (int j = 0; j < 2; ++j) {
                    float lo, hi;
                    unpack2(acc[i * 2 + j], lo, hi);
                    const int c0 = 2 * (n + 64 * j + 128 * half);
                    float s0 = __fsub_rn(__fadd_rn(znr, wn[c0]),     __fadd_rn(lo, lo));
                    float s1 = __fsub_rn(__fadd_rn(znr, wn[c0 + 1]), __fadd_rn(hi, hi));
                    unsigned long long k0 =
                        ((unsigned long long)orderable(s0) << 32) | (unsigned)c0;
                    unsigned long long k1 =
                        ((unsigned long long)orderable(s1) << 32) | (unsigned)(c0 + 1);
                    if (k0 < key) key = k0;
                    if (k1 < key) key = k1;
                }
#pragma unroll
                for (int off = 16; off > 0; off >>= 1) {
                    unsigned long long o = __shfl_down_sync(0xFFFFFFFFu, key, off);
                    if (o < key) key = o;
                }
                if (lane == 0) part[r * 4 + wbit * 2 + half] = key;
            }
        }
        __syncthreads();

        // merge 4 partials per row -> code
        if (tid < 128) {
            unsigned long long k = part[tid * 4];
            unsigned long long o1 = part[tid * 4 + 1];
            unsigned long long o2 = part[tid * 4 + 2];
            unsigned long long o3 = part[tid * 4 + 3];
            if (o1 < k) k = o1;
            if (o2 < k) k = o2;
            if (o3 < k) k = o3;
            int code = (int)(unsigned)(k & 0xFFFFFFFFULL);
            rcd[tid] = code;
            dout[OFF_CODE + (size_t)(n0 + tid)] = (float)code;
            atomicAdd(&hist[code], 1);
        }
        __syncthreads();

        // zq + loss (coalesced by r)
        float* zqg = dout + OFF_ZQ + (size_t)b * BCH + rem;
#pragma unroll
        for (int pass = 0; pass < 16; ++pass) {
            int d  = pass * 4 + (tid >> 7);
            int rr = tid & 127;
            int code = rcd[rr];
            float zv = zt[((d >> 1) * 128 + rr) * 2 + (d & 1)];
            float wv = wp[d * 512 + code];
            float df = __fsub_rn(wv, zv);
            ls = fmaf(df, df, ls);
            zqg[((size_t)d << 12) + rr] = __fadd_rn(zv, df);
        }

        // encodings one-hot (float2, 8B-aligned region)
        float2* encp = (float2*)(dout + OFF_ENC);
#pragma unroll 8
        for (int pass = 0; pass < 64; ++pass) {
            int e  = pass * 512 + tid;
            int rr = e >> 8;
            int c2 = e & 255;
            int code = rcd[rr];
            float2 v = make_float2(0.0f, 0.0f);
            if (c2 == (code >> 1)) { if (code & 1) v.y = 1.0f; else v.x = 1.0f; }
            encp[(size_t)(n0 + rr) * 256 + c2] = v;
        }
    }

    // ---- per-block partials ----
    __syncthreads();
    float lw = ls;
#pragma unroll
    for (int off = 16; off > 0; off >>= 1)
        lw += __shfl_down_sync(0xFFFFFFFFu, lw, off);
    if (lane == 0) lred[wid] = lw;
    __syncthreads();
    if (tid == 0) {
        float t = 0.0f;
#pragma unroll
        for (int i = 0; i < 16; ++i) t += lred[i];
        g_loss_part[blockIdx.x] = t;
    }
    g_hist_part[blockIdx.x * KCODE + tid] = hist[tid];

    // ---- last-block finalize (graph-replay safe: resets g_done) ----
    __threadfence();
    if (tid == 0) *sfin = (atomicAdd(&g_done, 1u) == GRID - 1);
    __syncthreads();
    if (*sfin) {
        int cnt = 0;
        for (int bb = 0; bb < GRID; ++bb) cnt += g_hist_part[bb * KCODE + tid];
        float em = (float)cnt * (1.0f / 131072.0f);
        float v  = em * logf(__fadd_rn(em, 1e-10f));
#pragma unroll
        for (int off = 16; off > 0; off >>= 1)
            v += __shfl_down_sync(0xFFFFFFFFu, v, off);
        if (lane == 0) lred[wid] = v;
        __syncthreads();
        if (wid == 0) {
            float s = (lane < 16) ? lred[lane] : 0.0f;
#pragma unroll
            for (int off = 8; off > 0; off >>= 1)
                s += __shfl_down_sync(0xFFFFFFFFu, s, off);
            if (lane == 0) dout[OFF_PERP] = expf(-s);
        }
        if (wid == 1) {
            float s = 0.0f;
            for (int i = lane; i < GRID; i += 32) s += g_loss_part[i];
#pragma unroll
            for (int off = 16; off > 0; off >>= 1)
                s += __shfl_down_sync(0xFFFFFFFFu, s, off);
            if (lane == 0) {
                float m = s * (1.0f / 8388608.0f);
                dout[OFF_LOSS] = __fadd_rn(m, __fmul_rn(0.25f, m));
            }
        }
        __syncthreads();
        if (tid == 0) g_done = 0;
    }
}

extern "C" void kernel_launch(void* const* d_in, const int* in_sizes, int n_in,
                              void* d_out, int out_size) {
    const float* z = (const float*)d_in[0];
    const float* w = (const float*)d_in[1];
    float* out = (float*)d_out;

    cudaFuncSetAttribute(vq_fused, cudaFuncAttributeMaxDynamicSharedMemorySize,
                         S_TOT * 4);
    vq_fused<<<GRID, TPB, S_TOT * 4>>>(z, w, out);
}